// round 15
// baseline (speedup 1.0000x reference)
#include <cuda_runtime.h>
#include <cuda_bf16.h>
#include <cuda_fp16.h>
#include <math.h>
#include <stdint.h>

// Problem constants (fixed by the dataset)
#define BB 8
#define LL 4096
#define DD 768
#define HH 512
#define NTOK (BB * LL)          // 32768
#define POOLED_ELEMS (BB * LL * DD)

// Arch-specific feature gate (proven live on this bench in R6).
#if defined(__CUDA_ARCH__) && (defined(__CUDA_ARCH_FEAT_SM103_ALL) || \
    defined(__CUDA_ARCH_FEAT_SM100_ALL) || defined(__CUDA_ARCH_SPECIFIC__) || \
    defined(__CUDA_ARCH_FAMILY_SPECIFIC__))
#define HAS_TC05 1
#else
#define HAS_TC05 0
#endif

#define KC 32
#define NUM_CHUNK (DD / KC)      // 24
#define NT_ITER (NUM_CHUNK * 2)  // 48 slot-sized work units (chunk x nhalf)
#define NSLOT 5                  // B ring depth (32KB each)
#define BBLK 32768               // one pre-swizzled B n-half block (256 rows x 128B)

// Device scratch (no allocations allowed)
__device__ float         g_logits[NTOK];
__device__ int           g_segstart[NTOK];   // per batch: start token of segment s
__device__ int           g_nseg[BB];
__device__ int           g_bcnt[BB];
__device__ int           g_done;             // scan completion counter (self-resetting)
// Pre-swizzled B tiles: [chunk][nhalf][32KB], byte-exact SMEM SW128 layout.
// Row n (0..255): [f16(w) x32 | f16(w - f16(w)) x32], swizzled.
__device__ __align__(128) unsigned char g_w1s[NUM_CHUNK * 2 * BBLK];

// ---------------------------------------------------------------------------
// Common helpers
// ---------------------------------------------------------------------------
__device__ __forceinline__ unsigned cvt_tf32(float f) {
    unsigned r;
    asm("cvt.rna.tf32.f32 %0, %1;" : "=r"(r) : "f"(f));
    return r;
}
__device__ __forceinline__ uint32_t smem_u32(const void* p) {
    uint32_t a;
    asm("{ .reg .u64 t; cvta.to.shared.u64 t, %1; cvt.u32.u64 %0, t; }" : "=r"(a) : "l"(p));
    return a;
}
__device__ __forceinline__ uint32_t sw128(uint32_t off) {
    return off ^ ((off >> 3) & 0x70);
}

// ---------------------------------------------------------------------------
// K-pre (tcgen05 path only): W1 [DD,HH] -> pre-swizzled f16 hi/lo tile blocks.
// ---------------------------------------------------------------------------
__global__ __launch_bounds__(256) void w1prep_kernel(const float* __restrict__ W1) {
#if HAS_TC05
    int idx = blockIdx.x * 256 + threadIdx.x;      // 0..98303
    int chunk = idx >> 12;                         // 24 chunks
    int q = idx & 4095;
    int n = q >> 3;                                // 0..511 (global hidden unit)
    int c = q & 7;                                 // c<4: hi groups, c>=4: lo
    int h = n >> 8;                                // n-half
    int nn = n & 255;
    int k0 = chunk * KC + (c & 3) * 8;

    __half out[8];
    #pragma unroll
    for (int j = 0; j < 8; ++j) {
        float w = W1[(size_t)(k0 + j) * HH + n];
        __half hi = __float2half_rn(w);
        out[j] = (c < 4) ? hi : __float2half_rn(w - __half2float(hi));
    }
    unsigned char* dst = g_w1s + ((size_t)(chunk * 2 + h)) * BBLK
                       + sw128((uint32_t)(nn * 128 + c * 16));
    *(uint4*)dst = *(const uint4*)out;
#endif
}

// ===========================================================================
// PATH A: tcgen05 GEMM, f16x3 split. Per CTA: M=128, N=512 in a SINGLE
// K-sweep. Work unit = (chunk, nhalf) = one 32KB pre-swizzled B slot.
// B ring: 5 slots, each with full/empty mbar pair (cp.async.bulk producer,
// MMA consumer). A ring: 2 x 16KB, thread-side staged, freed per-chunk via
// tcgen05.commit. Single 'done' mbar drains the whole MMA queue at the end.
// ===========================================================================
#define OFF_TMEMPTR 0
#define OFF_DONE    8
#define OFF_EB      16                  // empty_b[5]
#define OFF_FB      64                  // full_b[5]
#define OFF_EA      112                 // empty_a[2]
#define OFF_B1S     128
#define OFF_W2S     (128 + 2048)
#define OFF_RED     4224                // 128 rows x 2 halves x 4B
#define OFF_ASTG    6144                // 2 x 16KB
#define OFF_BSTG    39936               // 5 x 32KB (1024-aligned)
#define SMEM_TOTAL  (OFF_BSTG + NSLOT * BBLK + 1024)

#if HAS_TC05
__device__ __forceinline__ uint32_t elect_one() {
    uint32_t p;
    asm volatile("{\n\t.reg .pred p;\n\telect.sync _|p, 0xFFFFFFFF;\n\tselp.b32 %0, 1, 0, p;\n\t}" : "=r"(p));
    return p;
}
__device__ __forceinline__ uint64_t make_sw128_desc(uint32_t addr) {
    const uint64_t base = (2ull << 61) | (1ull << 46) | (64ull << 32) | (1ull << 16);
    return base | ((uint64_t)(addr >> 4) & 0x3FFF);
}
__device__ __forceinline__ void tc05_mma_f16_ss(uint32_t d_tmem, uint64_t a_desc,
                                                uint64_t b_desc, uint32_t idesc,
                                                uint32_t enable) {
    asm volatile(
        "{\n\t.reg .pred p;\n\tsetp.ne.u32 p, %5, 0;\n\t"
        "tcgen05.mma.cta_group::1.kind::f16 [%0], %1, %2, %3, {%4, %4, %4, %4}, p;\n\t}"
        :: "r"(d_tmem), "l"(a_desc), "l"(b_desc), "r"(idesc), "r"(0u), "r"(enable)
        : "memory");
}
#define MBAR_INIT(addr, cnt) \
    asm volatile("mbarrier.init.shared.b64 [%0], %1;" :: "r"(addr), "r"(cnt) : "memory")
#define MBAR_EXPECT_TX(addr, tx) \
    asm volatile("mbarrier.arrive.expect_tx.shared.b64 _, [%0], %1;" \
                 :: "r"(addr), "r"(tx) : "memory")
#define BULK_G2S(dst, src, bytes, mbar) \
    asm volatile("cp.async.bulk.shared::cta.global.mbarrier::complete_tx::bytes " \
                 "[%0], [%1], %2, [%3];" \
                 :: "r"(dst), "l"(src), "r"(bytes), "r"(mbar) : "memory")
#define TC05_COMMIT(addr) \
    asm volatile("tcgen05.commit.cta_group::1.mbarrier::arrive::one.shared::cluster.b64 [%0];" \
                 :: "r"(addr) : "memory")
#define MBAR_WAIT(addr, ph) do {                                                   \
    uint32_t _m = (addr), _p = (ph), _d;                                           \
    asm volatile("{\n\t.reg .pred p;\n\t"                                          \
        "mbarrier.try_wait.parity.acquire.cta.shared::cta.b64 p, [%1], %2;\n\t"    \
        "selp.b32 %0, 1, 0, p;\n\t}" : "=r"(_d) : "r"(_m), "r"(_p) : "memory");    \
    if (!_d) {                                                                     \
        asm volatile("{\n\t.reg .pred P1;\n\t"                                     \
            "W_%=:\n\t"                                                            \
            "mbarrier.try_wait.parity.acquire.cta.shared::cta.b64 P1, [%0], %1, 0x989680;\n\t" \
            "@P1 bra.uni D_%=;\n\tbra.uni W_%=;\n\tD_%=:\n\t}"                     \
            :: "r"(_m), "r"(_p) : "memory");                                       \
    } } while (0)
#define FENCE_ASYNC() asm volatile("fence.proxy.async.shared::cta;" ::: "memory")
#define TC05_FENCE_AFTER() asm volatile("tcgen05.fence::after_thread_sync;" ::: "memory")
#define TC05_FENCE_BEFORE() asm volatile("tcgen05.fence::before_thread_sync;" ::: "memory")
#define TC05_WAIT_LD() asm volatile("tcgen05.wait::ld.sync.aligned;" ::: "memory")
#define TC05_LD_X32(r, a)                                                          \
    asm volatile("tcgen05.ld.sync.aligned.32x32b.x32.b32 "                         \
        "{%0, %1, %2, %3, %4, %5, %6, %7, %8, %9, %10, %11, %12, %13, %14, %15, "  \
        " %16, %17, %18, %19, %20, %21, %22, %23, %24, %25, %26, %27, %28, %29, %30, %31}, [%32];" \
        : "=r"((r)[0]), "=r"((r)[1]), "=r"((r)[2]), "=r"((r)[3]),                  \
          "=r"((r)[4]), "=r"((r)[5]), "=r"((r)[6]), "=r"((r)[7]),                  \
          "=r"((r)[8]), "=r"((r)[9]), "=r"((r)[10]), "=r"((r)[11]),                \
          "=r"((r)[12]), "=r"((r)[13]), "=r"((r)[14]), "=r"((r)[15]),              \
          "=r"((r)[16]), "=r"((r)[17]), "=r"((r)[18]), "=r"((r)[19]),              \
          "=r"((r)[20]), "=r"((r)[21]), "=r"((r)[22]), "=r"((r)[23]),              \
          "=r"((r)[24]), "=r"((r)[25]), "=r"((r)[26]), "=r"((r)[27]),              \
          "=r"((r)[28]), "=r"((r)[29]), "=r"((r)[30]), "=r"((r)[31])               \
        : "r"(a))

// idesc: dtype F32, atype/btype F16(0), N=256, M=128
#define IDESC_F16  ((1u << 4) | ((256 / 8) << 17) | ((128 / 16) << 24))
#endif // HAS_TC05

__global__ __launch_bounds__(256, 1)
void gemm_logits_tc05_kernel(
    const float* __restrict__ X,   // [NTOK, DD]
    const float* __restrict__ b1,  // [HH]
    const float* __restrict__ W2,  // [HH]
    const float* __restrict__ b2)  // [1]
{
#if HAS_TC05
    extern __shared__ char dsm[];
    const uint32_t smem_raw = smem_u32(dsm);
    const uint32_t sb = (smem_raw + 1023u) & ~1023u;
    char* base = dsm + (sb - smem_raw);
    const int tid = threadIdx.x;
    const int lane = tid & 31;
    const int wid = tid >> 5;
    const int m0 = blockIdx.x * 128;

    if (wid == 0) {
        asm volatile("tcgen05.alloc.cta_group::1.sync.aligned.shared::cta.b32 [%0], %1;"
                     :: "r"(sb + OFF_TMEMPTR), "r"(512u) : "memory");
    }
    if (tid == 0) {
        MBAR_INIT(sb + OFF_DONE, 1);
        #pragma unroll
        for (int k = 0; k < NSLOT; ++k) {
            MBAR_INIT(sb + OFF_EB + 8 * k, 1);
            MBAR_INIT(sb + OFF_FB + 8 * k, 1);
        }
        MBAR_INIT(sb + OFF_EA, 1);
        MBAR_INIT(sb + OFF_EA + 8, 1);
    }
    for (int i = tid; i < HH; i += 256) {
        *(float*)(base + OFF_B1S + i * 4) = b1[i];
        *(float*)(base + OFF_W2S + i * 4) = W2[i];
    }
    __syncthreads();
    uint32_t tmem_base;
    asm volatile("ld.shared.b32 %0, [%1];" : "=r"(tmem_base) : "r"(sb + OFF_TMEMPTR));

    for (int t = 0; t < NT_ITER; ++t) {
        const int chunk = t >> 1;
        const int nh = t & 1;
        const int k0 = chunk * KC;
        const int sB = t % NSLOT;
        const int uB = t / NSLOT;

        // ---- B producer: one elected thread, one 32KB bulk copy per unit
        if (wid == 5) {
            if (elect_one()) {
                if (uB > 0) MBAR_WAIT(sb + OFF_EB + 8 * sB, (uB - 1) & 1);
                MBAR_EXPECT_TX(sb + OFF_FB + 8 * sB, BBLK);
                BULK_G2S(sb + OFF_BSTG + sB * BBLK,
                         g_w1s + (size_t)(chunk * 2 + nh) * BBLK,
                         BBLK, sb + OFF_FB + 8 * sB);
            }
        }

        // ---- A staging (once per chunk, all warps)
        if (nh == 0) {
            const int a = chunk & 1;
            const int ua = chunk >> 1;
            if (chunk >= 2) MBAR_WAIT(sb + OFF_EA + 8 * a, (ua - 1) & 1);
            char* astg = base + OFF_ASTG + a * 16384;
            #pragma unroll
            for (int it = 0; it < 4; ++it) {
                int idx = tid + it * 256;          // 0..1023
                int r = idx >> 3;
                int c = idx & 7;
                float4 v = *(const float4*)(X + (size_t)(m0 + r) * DD + k0 + c * 4);
                __half2 h01 = __floats2half2_rn(v.x, v.y);
                __half2 h23 = __floats2half2_rn(v.z, v.w);
                float2 f01 = __half22float2(h01);
                float2 f23 = __half22float2(h23);
                __half2 l01 = __floats2half2_rn(v.x - f01.x, v.y - f01.y);
                __half2 l23 = __floats2half2_rn(v.z - f23.x, v.w - f23.y);
                uint32_t so = sw128((uint32_t)(r * 128 + c * 8));
                *(__half2*)(astg + so)     = h01;
                *(__half2*)(astg + so + 4) = h23;
                uint32_t sl = sw128((uint32_t)(r * 128 + 64 + c * 8));
                *(__half2*)(astg + sl)     = l01;
                *(__half2*)(astg + sl + 4) = l23;
            }
            FENCE_ASYNC();
            __syncthreads();
        }

        // ---- MMA consumer (warp 4)
        if (wid == 4) {
            MBAR_WAIT(sb + OFF_FB + 8 * sB, uB & 1);
            if (elect_one()) {
                uint64_t ad = make_sw128_desc(sb + OFF_ASTG + (chunk & 1) * 16384);
                uint64_t bd = make_sw128_desc(sb + OFF_BSTG + sB * BBLK);
                uint32_t dt = tmem_base + nh * 256;
                #pragma unroll
                for (int ks = 0; ks < 2; ++ks) {
                    uint32_t en = (chunk == 0 && ks == 0) ? 0u : 1u;
                    tc05_mma_f16_ss(dt, ad + ks * 2, bd + ks * 2, IDESC_F16, en);
                    tc05_mma_f16_ss(dt, ad + 4 + ks * 2, bd + ks * 2, IDESC_F16, 1u);
                    tc05_mma_f16_ss(dt, ad + ks * 2, bd + 4 + ks * 2, IDESC_F16, 1u);
                }
                TC05_COMMIT(sb + OFF_EB + 8 * sB);            // free B slot
                if (nh == 1) TC05_COMMIT(sb + OFF_EA + 8 * (chunk & 1)); // free A slot
                if (t == NT_ITER - 1) TC05_COMMIT(sb + OFF_DONE);
            }
        }
    }

    // ---- drain: single done barrier covers the entire MMA queue
    MBAR_WAIT(sb + OFF_DONE, 0);
    TC05_FENCE_AFTER();

    // ---- epilogue: warps 0-3 read n-half 0, warps 4-7 read n-half 1
    {
        const float* b1s = (const float*)(base + OFF_B1S);
        const float* w2s = (const float*)(base + OFF_W2S);
        float* red = (float*)(base + OFF_RED);
        const int half = wid >> 2;
        const int row = (wid & 3) * 32 + lane;
        float s = 0.f;
        const uint32_t dtb = tmem_base + half * 256;
        #pragma unroll
        for (int cb = 0; cb < 8; ++cb) {
            uint32_t d[32];
            TC05_LD_X32(d, dtb + cb * 32);
            TC05_WAIT_LD();
            #pragma unroll
            for (int c = 0; c < 32; ++c) {
                int n = half * 256 + cb * 32 + c;
                s += fmaxf(__uint_as_float(d[c]) + b1s[n], 0.f) * w2s[n];
            }
        }
        TC05_FENCE_BEFORE();
        red[row * 2 + half] = s;
        __syncthreads();
        if (tid < 128) {
            g_logits[m0 + tid] = red[tid * 2] + red[tid * 2 + 1] + b2[0];
        }
    }

    __syncthreads();
    if (wid == 0) {
        asm volatile("tcgen05.relinquish_alloc_permit.cta_group::1.sync.aligned;");
        asm volatile("tcgen05.dealloc.cta_group::1.sync.aligned.b32 %0, %1;"
                     :: "r"(tmem_base), "r"(512u));
    }
#endif // HAS_TC05
}

// ===========================================================================
// PATH B: mma.sync fallback (launched only if the tc05 kernel is a stub)
// ===========================================================================
#define MT 128
#define NT 128
#define KT 32
#define AS_STRIDE 36
#define BS_STRIDE 136

#if !HAS_TC05
__device__ __forceinline__ void mma_tf32(float* d, unsigned a0, unsigned a1,
                                         unsigned a2, unsigned a3,
                                         unsigned b0, unsigned b1) {
    asm volatile(
        "mma.sync.aligned.m16n8k8.row.col.f32.tf32.tf32.f32 "
        "{%0,%1,%2,%3}, {%4,%5,%6,%7}, {%8,%9}, {%0,%1,%2,%3};"
        : "+f"(d[0]), "+f"(d[1]), "+f"(d[2]), "+f"(d[3])
        : "r"(a0), "r"(a1), "r"(a2), "r"(a3), "r"(b0), "r"(b1));
}
#endif

__global__ __launch_bounds__(256) void gemm_logits_fb_kernel(
    const float* __restrict__ X,   // [NTOK, DD]
    const float* __restrict__ W1,  // [DD, HH]
    const float* __restrict__ b1,  // [HH]
    const float* __restrict__ W2,  // [HH]
    const float* __restrict__ b2)  // [1]
{
#if !HAS_TC05
    __shared__ float As2[MT][AS_STRIDE];
    __shared__ float Bs2[KT][BS_STRIDE];
    __shared__ float red[MT][4];

    const int tid = threadIdx.x;
    const int lane = tid & 31;
    const int wid = tid >> 5;
    const int warp_m = wid & 1;
    const int warp_n = wid >> 1;
    const int g = lane >> 2;
    const int t = lane & 3;
    const int m0 = blockIdx.x * MT;

    float s[4][2];
    #pragma unroll
    for (int mf = 0; mf < 4; ++mf) { s[mf][0] = 0.f; s[mf][1] = 0.f; }

    for (int nc = 0; nc < HH / NT; ++nc) {
        const int nbase = nc * NT;

        float acc[4][4][4];
        #pragma unroll
        for (int mf = 0; mf < 4; ++mf)
            #pragma unroll
            for (int nf = 0; nf < 4; ++nf)
                #pragma unroll
                for (int e = 0; e < 4; ++e) acc[mf][nf][e] = 0.f;

        for (int k0 = 0; k0 < DD; k0 += KT) {
            __syncthreads();
            #pragma unroll
            for (int it = 0; it < 4; ++it) {
                int idx = tid + it * 256;
                int row = idx >> 3, c4 = idx & 7;
                float4 v = *(const float4*)(X + (size_t)(m0 + row) * DD + k0 + c4 * 4);
                *(float4*)&As2[row][c4 * 4] = v;
            }
            #pragma unroll
            for (int it = 0; it < 4; ++it) {
                int idx = tid + it * 256;
                int row = idx >> 5, c4 = idx & 31;
                float4 v = *(const float4*)(W1 + (size_t)(k0 + row) * HH + nbase + c4 * 4);
                *(float4*)&Bs2[row][c4 * 4] = v;
            }
            __syncthreads();

            #pragma unroll
            for (int ks = 0; ks < KT / 8; ++ks) {
                const int kb = ks * 8;
                unsigned ahi[4][4], alo[4][4];
                #pragma unroll
                for (int mf = 0; mf < 4; ++mf) {
                    const int r = warp_m * 64 + mf * 16 + g;
                    float f0 = As2[r][kb + t];
                    float f1 = As2[r + 8][kb + t];
                    float f2 = As2[r][kb + t + 4];
                    float f3 = As2[r + 8][kb + t + 4];
                    ahi[mf][0] = cvt_tf32(f0);
                    ahi[mf][1] = cvt_tf32(f1);
                    ahi[mf][2] = cvt_tf32(f2);
                    ahi[mf][3] = cvt_tf32(f3);
                    alo[mf][0] = cvt_tf32(f0 - __uint_as_float(ahi[mf][0]));
                    alo[mf][1] = cvt_tf32(f1 - __uint_as_float(ahi[mf][1]));
                    alo[mf][2] = cvt_tf32(f2 - __uint_as_float(ahi[mf][2]));
                    alo[mf][3] = cvt_tf32(f3 - __uint_as_float(ahi[mf][3]));
                }
                #pragma unroll
                for (int nf = 0; nf < 4; ++nf) {
                    const int col = warp_n * 32 + nf * 8 + g;
                    float fb0 = Bs2[kb + t][col];
                    float fb1 = Bs2[kb + t + 4][col];
                    unsigned bhi0 = cvt_tf32(fb0);
                    unsigned bhi1 = cvt_tf32(fb1);
                    unsigned blo0 = cvt_tf32(fb0 - __uint_as_float(bhi0));
                    unsigned blo1 = cvt_tf32(fb1 - __uint_as_float(bhi1));
                    #pragma unroll
                    for (int mf = 0; mf < 4; ++mf) {
                        mma_tf32(acc[mf][nf], ahi[mf][0], ahi[mf][1], ahi[mf][2], ahi[mf][3], bhi0, bhi1);
                        mma_tf32(acc[mf][nf], alo[mf][0], alo[mf][1], alo[mf][2], alo[mf][3], bhi0, bhi1);
                        mma_tf32(acc[mf][nf], ahi[mf][0], ahi[mf][1], ahi[mf][2], ahi[mf][3], blo0, blo1);
                    }
                }
            }
        }

        #pragma unroll
        for (int nf = 0; nf < 4; ++nf) {
            const int c0 = nbase + warp_n * 32 + nf * 8 + t * 2;
            const float bb0 = b1[c0],     bb1 = b1[c0 + 1];
            const float w0  = W2[c0],     w1  = W2[c0 + 1];
            #pragma unroll
            for (int mf = 0; mf < 4; ++mf) {
                s[mf][0] += fmaxf(acc[mf][nf][0] + bb0, 0.f) * w0
                          + fmaxf(acc[mf][nf][1] + bb1, 0.f) * w1;
                s[mf][1] += fmaxf(acc[mf][nf][2] + bb0, 0.f) * w0
                          + fmaxf(acc[mf][nf][3] + bb1, 0.f) * w1;
            }
        }
    }

    #pragma unroll
    for (int mf = 0; mf < 4; ++mf) {
        #pragma unroll
        for (int h = 0; h < 2; ++h) {
            float v = s[mf][h];
            v += __shfl_down_sync(0xffffffffu, v, 1);
            v += __shfl_down_sync(0xffffffffu, v, 2);
            s[mf][h] = v;
        }
    }
    __syncthreads();
    if (t == 0) {
        #pragma unroll
        for (int mf = 0; mf < 4; ++mf) {
            const int r = warp_m * 64 + mf * 16 + g;
            red[r][warp_n] = s[mf][0];
            red[r + 8][warp_n] = s[mf][1];
        }
    }
    __syncthreads();
    if (tid < MT) {
        float v = red[tid][0] + red[tid][1] + red[tid][2] + red[tid][3];
        g_logits[m0 + tid] = v + b2[0];
    }
#endif // !HAS_TC05
}

// ---------------------------------------------------------------------------
// K2: per-batch boundary sample + scan + segment starts + fused scalars.
// ---------------------------------------------------------------------------
__global__ __launch_bounds__(1024) void scan_kernel(
    const float* __restrict__ noise_u, float* __restrict__ outs)
{
    const int b = blockIdx.x;
    const int tid = threadIdx.x;
    const int l0 = tid * 4;
    const int base = b * LL + l0;

    int hd[4];
    #pragma unroll
    for (int j = 0; j < 4; ++j) {
        float u = noise_u[base + j];
        float x = g_logits[base + j] + logf(u) - log1pf(-u);
        hd[j] = (x > 0.f) ? 1 : 0;
    }
    int p = hd[0] + hd[1] + hd[2] + hd[3];

    const int lane = tid & 31;
    const int warp = tid >> 5;
    int v = p;
    #pragma unroll
    for (int off = 1; off < 32; off <<= 1) {
        int n = __shfl_up_sync(0xffffffffu, v, off);
        if (lane >= off) v += n;
    }
    __shared__ int wsum[32];
    if (lane == 31) wsum[warp] = v;
    __syncthreads();
    if (warp == 0) {
        int w = wsum[lane];
        #pragma unroll
        for (int off = 1; off < 32; off <<= 1) {
            int n = __shfl_up_sync(0xffffffffu, w, off);
            if (lane >= off) w += n;
        }
        wsum[lane] = w;
    }
    __syncthreads();

    int excl = (warp ? wsum[warp - 1] : 0) + v - p;   // boundaries strictly before l0
    int run = excl;                                    // = seg id of current token
    if (tid == 0) g_segstart[b * LL] = 0;
    #pragma unroll
    for (int j = 0; j < 4; ++j) {
        if (hd[j]) {
            int nxt = l0 + j + 1;
            if (nxt < LL) g_segstart[b * LL + run + 1] = nxt;
        }
        run += hd[j];
    }
    if (tid == 1023) {
        g_bcnt[b] = run;
        g_nseg[b] = run - hd[3] + 1;
        __threadfence();
        int done = atomicAdd(&g_done, 1);
        if (done == BB - 1) {
            int nb = 0;
            #pragma unroll
            for (int i = 0; i < BB; ++i) nb += g_bcnt[i];
            float ratio = (float)nb / (float)NTOK;
            outs[0] = fmaxf(fabsf(ratio - 0.25f) - 0.05f, 0.f);
            outs[1] = (float)nb;
            outs[2] = (float)NTOK;
            atomicExch(&g_done, 0);
        }
    }
}

// ---------------------------------------------------------------------------
// K4: pooled output — one warp per OUTPUT row (b, s). Covers all rows.
// ---------------------------------------------------------------------------
__global__ __launch_bounds__(128) void pool_kernel(
    const float* __restrict__ hidden, float* __restrict__ out)
{
    const int gwarp = (blockIdx.x * blockDim.x + threadIdx.x) >> 5;
    const int lane = threadIdx.x & 31;
    const int b = gwarp >> 12;          // / LL
    const int s = gwarp & (LL - 1);     // % LL

    float4 acc[6];
    #pragma unroll
    for (int i = 0; i < 6; ++i) acc[i] = make_float4(0.f, 0.f, 0.f, 0.f);

    const int nseg = g_nseg[b];
    if (s < nseg) {
        const int start = g_segstart[b * LL + s];
        const int end = (s + 1 < nseg) ? g_segstart[b * LL + s + 1] : LL;
        const float4* row = (const float4*)(hidden + ((size_t)b * LL + start) * DD);
        #pragma unroll 2
        for (int j = start; j < end; ++j, row += DD / 4) {
            #pragma unroll
            for (int i = 0; i < 6; ++i) {
                float4 r = row[lane + 32 * i];
                acc[i].x += r.x; acc[i].y += r.y; acc[i].z += r.z; acc[i].w += r.w;
            }
        }
        const float inv = 1.0f / (float)(end - start);
        #pragma unroll
        for (int i = 0; i < 6; ++i) {
            acc[i].x *= inv; acc[i].y *= inv; acc[i].z *= inv; acc[i].w *= inv;
        }
    }

    float4* orow = (float4*)(out + ((size_t)b * LL + s) * DD);
    #pragma unroll
    for (int i = 0; i < 6; ++i) orow[lane + 32 * i] = acc[i];
}

// ---------------------------------------------------------------------------
extern "C" void kernel_launch(void* const* d_in, const int* in_sizes, int n_in,
                              void* d_out, int out_size) {
    const float* hidden  = (const float*)d_in[0];
    const float* W1      = (const float*)d_in[1];
    const float* b1      = (const float*)d_in[2];
    const float* W2      = (const float*)d_in[3];
    const float* b2      = (const float*)d_in[4];
    const float* noise_u = (const float*)d_in[5];
    float* out = (float*)d_out;

    // Which GEMM has a body in the loaded cubin? (host code runs at capture time)
    cudaFuncAttributes attr;
    cudaFuncGetAttributes(&attr, gemm_logits_tc05_kernel);
    const bool tc05_live = attr.numRegs > 24;

    if (tc05_live) {
        cudaFuncSetAttribute(gemm_logits_tc05_kernel,
                             cudaFuncAttributeMaxDynamicSharedMemorySize, SMEM_TOTAL);
        w1prep_kernel<<<(NUM_CHUNK * 2 * BBLK / 16) / 256, 256>>>(W1);
        gemm_logits_tc05_kernel<<<NTOK / 128, 256, SMEM_TOTAL>>>(hidden, b1, W2, b2);
    } else {
        gemm_logits_fb_kernel<<<NTOK / MT, 256>>>(hidden, W1, b1, W2, b2);
    }
    scan_kernel<<<BB, 1024>>>(noise_u, out + (out_size - 3));
    pool_kernel<<<NTOK / 4, 128>>>(hidden, out);
}

// round 16
// speedup vs baseline: 1.2515x; 1.2515x over previous
#include <cuda_runtime.h>
#include <cuda_bf16.h>
#include <cuda_fp16.h>
#include <math.h>
#include <stdint.h>

// Problem constants (fixed by the dataset)
#define BB 8
#define LL 4096
#define DD 768
#define HH 512
#define NTOK (BB * LL)          // 32768
#define POOLED_ELEMS (BB * LL * DD)

// Arch-specific feature gate (proven live on this bench in R6).
#if defined(__CUDA_ARCH__) && (defined(__CUDA_ARCH_FEAT_SM103_ALL) || \
    defined(__CUDA_ARCH_FEAT_SM100_ALL) || defined(__CUDA_ARCH_SPECIFIC__) || \
    defined(__CUDA_ARCH_FAMILY_SPECIFIC__))
#define HAS_TC05 1
#else
#define HAS_TC05 0
#endif

#define KC 32
#define NUM_CHUNK (DD / KC)      // 24
#define NT_ITER (NUM_CHUNK * 2)  // 48 slot-sized work units (chunk x nhalf)
#define NSLOT 5                  // B ring depth (32KB each)
#define BBLK 32768               // one pre-swizzled B n-half block (256 rows x 128B)

// Device scratch (no allocations allowed)
__device__ float         g_logits[NTOK];
__device__ int           g_segstart[NTOK];   // per batch: start token of segment s
__device__ int           g_nseg[BB];
__device__ int           g_bcnt[BB];
__device__ int           g_done;             // scan completion counter (self-resetting)
// Pre-swizzled B tiles: [chunk][nhalf][32KB], byte-exact SMEM SW128 layout.
// Row n (0..255): [f16(w) x32 | f16(w - f16(w)) x32], swizzled.
__device__ __align__(128) unsigned char g_w1s[NUM_CHUNK * 2 * BBLK];

// ---------------------------------------------------------------------------
// Common helpers
// ---------------------------------------------------------------------------
__device__ __forceinline__ unsigned cvt_tf32(float f) {
    unsigned r;
    asm("cvt.rna.tf32.f32 %0, %1;" : "=r"(r) : "f"(f));
    return r;
}
__device__ __forceinline__ uint32_t smem_u32(const void* p) {
    uint32_t a;
    asm("{ .reg .u64 t; cvta.to.shared.u64 t, %1; cvt.u32.u64 %0, t; }" : "=r"(a) : "l"(p));
    return a;
}
__device__ __forceinline__ uint32_t sw128(uint32_t off) {
    return off ^ ((off >> 3) & 0x70);
}

// ---------------------------------------------------------------------------
// K-pre (tcgen05 path only): W1 [DD,HH] -> pre-swizzled f16 hi/lo tile blocks.
// ---------------------------------------------------------------------------
__global__ __launch_bounds__(256) void w1prep_kernel(const float* __restrict__ W1) {
#if HAS_TC05
    int idx = blockIdx.x * 256 + threadIdx.x;      // 0..98303
    int chunk = idx >> 12;                         // 24 chunks
    int q = idx & 4095;
    int n = q >> 3;                                // 0..511 (global hidden unit)
    int c = q & 7;                                 // c<4: hi groups, c>=4: lo
    int h = n >> 8;                                // n-half
    int nn = n & 255;
    int k0 = chunk * KC + (c & 3) * 8;

    __half out[8];
    #pragma unroll
    for (int j = 0; j < 8; ++j) {
        float w = W1[(size_t)(k0 + j) * HH + n];
        __half hi = __float2half_rn(w);
        out[j] = (c < 4) ? hi : __float2half_rn(w - __half2float(hi));
    }
    unsigned char* dst = g_w1s + ((size_t)(chunk * 2 + h)) * BBLK
                       + sw128((uint32_t)(nn * 128 + c * 16));
    *(uint4*)dst = *(const uint4*)out;
#endif
}

// ===========================================================================
// PATH A: tcgen05 GEMM, f16x3 split, WARP-SPECIALIZED (no CTA barrier in
// the mainloop). Per CTA: M=128, N=512, single K-sweep.
//   warps 0-3 : A stagers  (2-deep 16KB ring; full_a count=128, empty_a via
//               tcgen05.commit from the MMA warp)
//   warp 4    : MMA consumer (work unit = (chunk, nhalf) = one B slot;
//               6 dispatches/unit; frees B slot + A buffer via commit)
//   warp 5    : B producer (elected thread; 5-slot 32KB cp.async.bulk ring)
//   warps 6-7 : idle until drain; all 8 warps run the epilogue.
// ===========================================================================
#define OFF_TMEMPTR 0
#define OFF_DONE    8
#define OFF_EB      16                  // empty_b[5]
#define OFF_FB      64                  // full_b[5]
#define OFF_EA      112                 // empty_a[2]
#define OFF_FA      128                 // full_a[2]
#define OFF_B1S     192
#define OFF_W2S     (192 + 2048)
#define OFF_RED     4352                // 128 rows x 2 halves x 4B
#define OFF_ASTG    6144                // 2 x 16KB
#define OFF_BSTG    39936               // 5 x 32KB (1024-aligned)
#define SMEM_TOTAL  (OFF_BSTG + NSLOT * BBLK + 1024)

#if HAS_TC05
__device__ __forceinline__ uint32_t elect_one() {
    uint32_t p;
    asm volatile("{\n\t.reg .pred p;\n\telect.sync _|p, 0xFFFFFFFF;\n\tselp.b32 %0, 1, 0, p;\n\t}" : "=r"(p));
    return p;
}
__device__ __forceinline__ uint64_t make_sw128_desc(uint32_t addr) {
    const uint64_t base = (2ull << 61) | (1ull << 46) | (64ull << 32) | (1ull << 16);
    return base | ((uint64_t)(addr >> 4) & 0x3FFF);
}
__device__ __forceinline__ void tc05_mma_f16_ss(uint32_t d_tmem, uint64_t a_desc,
                                                uint64_t b_desc, uint32_t idesc,
                                                uint32_t enable) {
    asm volatile(
        "{\n\t.reg .pred p;\n\tsetp.ne.u32 p, %5, 0;\n\t"
        "tcgen05.mma.cta_group::1.kind::f16 [%0], %1, %2, %3, {%4, %4, %4, %4}, p;\n\t}"
        :: "r"(d_tmem), "l"(a_desc), "l"(b_desc), "r"(idesc), "r"(0u), "r"(enable)
        : "memory");
}
#define MBAR_INIT(addr, cnt) \
    asm volatile("mbarrier.init.shared.b64 [%0], %1;" :: "r"(addr), "r"(cnt) : "memory")
#define MBAR_ARRIVE(addr) \
    asm volatile("mbarrier.arrive.shared.b64 _, [%0];" :: "r"(addr) : "memory")
#define MBAR_EXPECT_TX(addr, tx) \
    asm volatile("mbarrier.arrive.expect_tx.shared.b64 _, [%0], %1;" \
                 :: "r"(addr), "r"(tx) : "memory")
#define BULK_G2S(dst, src, bytes, mbar) \
    asm volatile("cp.async.bulk.shared::cta.global.mbarrier::complete_tx::bytes " \
                 "[%0], [%1], %2, [%3];" \
                 :: "r"(dst), "l"(src), "r"(bytes), "r"(mbar) : "memory")
#define TC05_COMMIT(addr) \
    asm volatile("tcgen05.commit.cta_group::1.mbarrier::arrive::one.shared::cluster.b64 [%0];" \
                 :: "r"(addr) : "memory")
#define MBAR_WAIT(addr, ph) do {                                                   \
    uint32_t _m = (addr), _p = (ph), _d;                                           \
    asm volatile("{\n\t.reg .pred p;\n\t"                                          \
        "mbarrier.try_wait.parity.acquire.cta.shared::cta.b64 p, [%1], %2;\n\t"    \
        "selp.b32 %0, 1, 0, p;\n\t}" : "=r"(_d) : "r"(_m), "r"(_p) : "memory");    \
    if (!_d) {                                                                     \
        asm volatile("{\n\t.reg .pred P1;\n\t"                                     \
            "W_%=:\n\t"                                                            \
            "mbarrier.try_wait.parity.acquire.cta.shared::cta.b64 P1, [%0], %1, 0x989680;\n\t" \
            "@P1 bra.uni D_%=;\n\tbra.uni W_%=;\n\tD_%=:\n\t}"                     \
            :: "r"(_m), "r"(_p) : "memory");                                       \
    } } while (0)
#define FENCE_ASYNC() asm volatile("fence.proxy.async.shared::cta;" ::: "memory")
#define TC05_FENCE_AFTER() asm volatile("tcgen05.fence::after_thread_sync;" ::: "memory")
#define TC05_FENCE_BEFORE() asm volatile("tcgen05.fence::before_thread_sync;" ::: "memory")
#define TC05_WAIT_LD() asm volatile("tcgen05.wait::ld.sync.aligned;" ::: "memory")
#define TC05_LD_X32(r, a)                                                          \
    asm volatile("tcgen05.ld.sync.aligned.32x32b.x32.b32 "                         \
        "{%0, %1, %2, %3, %4, %5, %6, %7, %8, %9, %10, %11, %12, %13, %14, %15, "  \
        " %16, %17, %18, %19, %20, %21, %22, %23, %24, %25, %26, %27, %28, %29, %30, %31}, [%32];" \
        : "=r"((r)[0]), "=r"((r)[1]), "=r"((r)[2]), "=r"((r)[3]),                  \
          "=r"((r)[4]), "=r"((r)[5]), "=r"((r)[6]), "=r"((r)[7]),                  \
          "=r"((r)[8]), "=r"((r)[9]), "=r"((r)[10]), "=r"((r)[11]),                \
          "=r"((r)[12]), "=r"((r)[13]), "=r"((r)[14]), "=r"((r)[15]),              \
          "=r"((r)[16]), "=r"((r)[17]), "=r"((r)[18]), "=r"((r)[19]),              \
          "=r"((r)[20]), "=r"((r)[21]), "=r"((r)[22]), "=r"((r)[23]),              \
          "=r"((r)[24]), "=r"((r)[25]), "=r"((r)[26]), "=r"((r)[27]),              \
          "=r"((r)[28]), "=r"((r)[29]), "=r"((r)[30]), "=r"((r)[31])               \
        : "r"(a))

// idesc: dtype F32, atype/btype F16(0), N=256, M=128
#define IDESC_F16  ((1u << 4) | ((256 / 8) << 17) | ((128 / 16) << 24))
#endif // HAS_TC05

__global__ __launch_bounds__(256, 1)
void gemm_logits_tc05_kernel(
    const float* __restrict__ X,   // [NTOK, DD]
    const float* __restrict__ b1,  // [HH]
    const float* __restrict__ W2,  // [HH]
    const float* __restrict__ b2)  // [1]
{
#if HAS_TC05
    extern __shared__ char dsm[];
    const uint32_t smem_raw = smem_u32(dsm);
    const uint32_t sb = (smem_raw + 1023u) & ~1023u;
    char* base = dsm + (sb - smem_raw);
    const int tid = threadIdx.x;
    const int lane = tid & 31;
    const int wid = tid >> 5;
    const int m0 = blockIdx.x * 128;

    if (wid == 0) {
        asm volatile("tcgen05.alloc.cta_group::1.sync.aligned.shared::cta.b32 [%0], %1;"
                     :: "r"(sb + OFF_TMEMPTR), "r"(512u) : "memory");
    }
    if (tid == 0) {
        MBAR_INIT(sb + OFF_DONE, 1);
        #pragma unroll
        for (int k = 0; k < NSLOT; ++k) {
            MBAR_INIT(sb + OFF_EB + 8 * k, 1);
            MBAR_INIT(sb + OFF_FB + 8 * k, 1);
        }
        #pragma unroll
        for (int k = 0; k < 2; ++k) {
            MBAR_INIT(sb + OFF_EA + 8 * k, 1);
            MBAR_INIT(sb + OFF_FA + 8 * k, 128);   // 4 stager warps x 32 lanes
        }
    }
    for (int i = tid; i < HH; i += 256) {
        *(float*)(base + OFF_B1S + i * 4) = b1[i];
        *(float*)(base + OFF_W2S + i * 4) = W2[i];
    }
    __syncthreads();
    uint32_t tmem_base;
    asm volatile("ld.shared.b32 %0, [%1];" : "=r"(tmem_base) : "r"(sb + OFF_TMEMPTR));

    // ================= role-specialized mainloop (no __syncthreads) ========
    if (wid < 4) {
        // ---- A stagers: 128 threads, 16KB per chunk, 2-deep ring
        const int wtid = tid;              // 0..127
        for (int chunk = 0; chunk < NUM_CHUNK; ++chunk) {
            const int a = chunk & 1;
            const int ua = chunk >> 1;
            const int k0 = chunk * KC;
            if (chunk >= 2) MBAR_WAIT(sb + OFF_EA + 8 * a, (ua - 1) & 1);
            char* astg = base + OFF_ASTG + a * 16384;
            #pragma unroll
            for (int it = 0; it < 8; ++it) {
                int idx = wtid + it * 128;         // 0..1023
                int r = idx >> 3;
                int c = idx & 7;
                float4 v = *(const float4*)(X + (size_t)(m0 + r) * DD + k0 + c * 4);
                __half2 h01 = __floats2half2_rn(v.x, v.y);
                __half2 h23 = __floats2half2_rn(v.z, v.w);
                float2 f01 = __half22float2(h01);
                float2 f23 = __half22float2(h23);
                __half2 l01 = __floats2half2_rn(v.x - f01.x, v.y - f01.y);
                __half2 l23 = __floats2half2_rn(v.z - f23.x, v.w - f23.y);
                uint32_t so = sw128((uint32_t)(r * 128 + c * 8));
                *(__half2*)(astg + so)     = h01;
                *(__half2*)(astg + so + 4) = h23;
                uint32_t sl = sw128((uint32_t)(r * 128 + 64 + c * 8));
                *(__half2*)(astg + sl)     = l01;
                *(__half2*)(astg + sl + 4) = l23;
            }
            FENCE_ASYNC();
            MBAR_ARRIVE(sb + OFF_FA + 8 * a);      // 128 arrivals flip the phase
        }
    } else if (wid == 4) {
        // ---- MMA consumer
        for (int t = 0; t < NT_ITER; ++t) {
            const int chunk = t >> 1;
            const int nh = t & 1;
            const int sB = t % NSLOT;
            const int uB = t / NSLOT;
            MBAR_WAIT(sb + OFF_FB + 8 * sB, uB & 1);
            if (nh == 0) MBAR_WAIT(sb + OFF_FA + 8 * (chunk & 1), (chunk >> 1) & 1);
            if (elect_one()) {
                uint64_t ad = make_sw128_desc(sb + OFF_ASTG + (chunk & 1) * 16384);
                uint64_t bd = make_sw128_desc(sb + OFF_BSTG + sB * BBLK);
                uint32_t dt = tmem_base + nh * 256;
                #pragma unroll
                for (int ks = 0; ks < 2; ++ks) {
                    uint32_t en = (chunk == 0 && ks == 0) ? 0u : 1u;
                    tc05_mma_f16_ss(dt, ad + ks * 2, bd + ks * 2, IDESC_F16, en);
                    tc05_mma_f16_ss(dt, ad + 4 + ks * 2, bd + ks * 2, IDESC_F16, 1u);
                    tc05_mma_f16_ss(dt, ad + ks * 2, bd + 4 + ks * 2, IDESC_F16, 1u);
                }
                TC05_COMMIT(sb + OFF_EB + 8 * sB);                       // free B slot
                if (nh == 1) TC05_COMMIT(sb + OFF_EA + 8 * (chunk & 1)); // free A buf
                if (t == NT_ITER - 1) TC05_COMMIT(sb + OFF_DONE);
            }
        }
    } else if (wid == 5) {
        // ---- B producer: elected thread only; stalls hurt nobody else
        if (elect_one()) {
            for (int t = 0; t < NT_ITER; ++t) {
                const int sB = t % NSLOT;
                const int uB = t / NSLOT;
                if (uB > 0) MBAR_WAIT(sb + OFF_EB + 8 * sB, (uB - 1) & 1);
                MBAR_EXPECT_TX(sb + OFF_FB + 8 * sB, BBLK);
                BULK_G2S(sb + OFF_BSTG + sB * BBLK,
                         g_w1s + (size_t)t * BBLK,   // t == chunk*2 + nh
                         BBLK, sb + OFF_FB + 8 * sB);
            }
        }
    }
    // (warps 6-7 fall straight through)

    // ---- drain: single done barrier covers the entire MMA queue
    MBAR_WAIT(sb + OFF_DONE, 0);
    TC05_FENCE_AFTER();

    // ---- epilogue: warps 0-3 read n-half 0, warps 4-7 read n-half 1
    {
        const float* b1s = (const float*)(base + OFF_B1S);
        const float* w2s = (const float*)(base + OFF_W2S);
        float* red = (float*)(base + OFF_RED);
        const int half = wid >> 2;
        const int row = (wid & 3) * 32 + lane;
        float s = 0.f;
        const uint32_t dtb = tmem_base + half * 256;
        #pragma unroll
        for (int cb = 0; cb < 8; ++cb) {
            uint32_t d[32];
            TC05_LD_X32(d, dtb + cb * 32);
            TC05_WAIT_LD();
            #pragma unroll
            for (int c = 0; c < 32; ++c) {
                int n = half * 256 + cb * 32 + c;
                s += fmaxf(__uint_as_float(d[c]) + b1s[n], 0.f) * w2s[n];
            }
        }
        TC05_FENCE_BEFORE();
        red[row * 2 + half] = s;
        __syncthreads();
        if (tid < 128) {
            g_logits[m0 + tid] = red[tid * 2] + red[tid * 2 + 1] + b2[0];
        }
    }

    __syncthreads();
    if (wid == 0) {
        asm volatile("tcgen05.relinquish_alloc_permit.cta_group::1.sync.aligned;");
        asm volatile("tcgen05.dealloc.cta_group::1.sync.aligned.b32 %0, %1;"
                     :: "r"(tmem_base), "r"(512u));
    }
#endif // HAS_TC05
}

// ===========================================================================
// PATH B: mma.sync fallback (launched only if the tc05 kernel is a stub)
// ===========================================================================
#define MT 128
#define NT 128
#define KT 32
#define AS_STRIDE 36
#define BS_STRIDE 136

#if !HAS_TC05
__device__ __forceinline__ void mma_tf32(float* d, unsigned a0, unsigned a1,
                                         unsigned a2, unsigned a3,
                                         unsigned b0, unsigned b1) {
    asm volatile(
        "mma.sync.aligned.m16n8k8.row.col.f32.tf32.tf32.f32 "
        "{%0,%1,%2,%3}, {%4,%5,%6,%7}, {%8,%9}, {%0,%1,%2,%3};"
        : "+f"(d[0]), "+f"(d[1]), "+f"(d[2]), "+f"(d[3])
        : "r"(a0), "r"(a1), "r"(a2), "r"(a3), "r"(b0), "r"(b1));
}
#endif

__global__ __launch_bounds__(256) void gemm_logits_fb_kernel(
    const float* __restrict__ X,   // [NTOK, DD]
    const float* __restrict__ W1,  // [DD, HH]
    const float* __restrict__ b1,  // [HH]
    const float* __restrict__ W2,  // [HH]
    const float* __restrict__ b2)  // [1]
{
#if !HAS_TC05
    __shared__ float As2[MT][AS_STRIDE];
    __shared__ float Bs2[KT][BS_STRIDE];
    __shared__ float red[MT][4];

    const int tid = threadIdx.x;
    const int lane = tid & 31;
    const int wid = tid >> 5;
    const int warp_m = wid & 1;
    const int warp_n = wid >> 1;
    const int g = lane >> 2;
    const int t = lane & 3;
    const int m0 = blockIdx.x * MT;

    float s[4][2];
    #pragma unroll
    for (int mf = 0; mf < 4; ++mf) { s[mf][0] = 0.f; s[mf][1] = 0.f; }

    for (int nc = 0; nc < HH / NT; ++nc) {
        const int nbase = nc * NT;

        float acc[4][4][4];
        #pragma unroll
        for (int mf = 0; mf < 4; ++mf)
            #pragma unroll
            for (int nf = 0; nf < 4; ++nf)
                #pragma unroll
                for (int e = 0; e < 4; ++e) acc[mf][nf][e] = 0.f;

        for (int k0 = 0; k0 < DD; k0 += KT) {
            __syncthreads();
            #pragma unroll
            for (int it = 0; it < 4; ++it) {
                int idx = tid + it * 256;
                int row = idx >> 3, c4 = idx & 7;
                float4 v = *(const float4*)(X + (size_t)(m0 + row) * DD + k0 + c4 * 4);
                *(float4*)&As2[row][c4 * 4] = v;
            }
            #pragma unroll
            for (int it = 0; it < 4; ++it) {
                int idx = tid + it * 256;
                int row = idx >> 5, c4 = idx & 31;
                float4 v = *(const float4*)(W1 + (size_t)(k0 + row) * HH + nbase + c4 * 4);
                *(float4*)&Bs2[row][c4 * 4] = v;
            }
            __syncthreads();

            #pragma unroll
            for (int ks = 0; ks < KT / 8; ++ks) {
                const int kb = ks * 8;
                unsigned ahi[4][4], alo[4][4];
                #pragma unroll
                for (int mf = 0; mf < 4; ++mf) {
                    const int r = warp_m * 64 + mf * 16 + g;
                    float f0 = As2[r][kb + t];
                    float f1 = As2[r + 8][kb + t];
                    float f2 = As2[r][kb + t + 4];
                    float f3 = As2[r + 8][kb + t + 4];
                    ahi[mf][0] = cvt_tf32(f0);
                    ahi[mf][1] = cvt_tf32(f1);
                    ahi[mf][2] = cvt_tf32(f2);
                    ahi[mf][3] = cvt_tf32(f3);
                    alo[mf][0] = cvt_tf32(f0 - __uint_as_float(ahi[mf][0]));
                    alo[mf][1] = cvt_tf32(f1 - __uint_as_float(ahi[mf][1]));
                    alo[mf][2] = cvt_tf32(f2 - __uint_as_float(ahi[mf][2]));
                    alo[mf][3] = cvt_tf32(f3 - __uint_as_float(ahi[mf][3]));
                }
                #pragma unroll
                for (int nf = 0; nf < 4; ++nf) {
                    const int col = warp_n * 32 + nf * 8 + g;
                    float fb0 = Bs2[kb + t][col];
                    float fb1 = Bs2[kb + t + 4][col];
                    unsigned bhi0 = cvt_tf32(fb0);
                    unsigned bhi1 = cvt_tf32(fb1);
                    unsigned blo0 = cvt_tf32(fb0 - __uint_as_float(bhi0));
                    unsigned blo1 = cvt_tf32(fb1 - __uint_as_float(bhi1));
                    #pragma unroll
                    for (int mf = 0; mf < 4; ++mf) {
                        mma_tf32(acc[mf][nf], ahi[mf][0], ahi[mf][1], ahi[mf][2], ahi[mf][3], bhi0, bhi1);
                        mma_tf32(acc[mf][nf], alo[mf][0], alo[mf][1], alo[mf][2], alo[mf][3], bhi0, bhi1);
                        mma_tf32(acc[mf][nf], ahi[mf][0], ahi[mf][1], ahi[mf][2], ahi[mf][3], blo0, blo1);
                    }
                }
            }
        }

        #pragma unroll
        for (int nf = 0; nf < 4; ++nf) {
            const int c0 = nbase + warp_n * 32 + nf * 8 + t * 2;
            const float bb0 = b1[c0],     bb1 = b1[c0 + 1];
            const float w0  = W2[c0],     w1  = W2[c0 + 1];
            #pragma unroll
            for (int mf = 0; mf < 4; ++mf) {
                s[mf][0] += fmaxf(acc[mf][nf][0] + bb0, 0.f) * w0
                          + fmaxf(acc[mf][nf][1] + bb1, 0.f) * w1;
                s[mf][1] += fmaxf(acc[mf][nf][2] + bb0, 0.f) * w0
                          + fmaxf(acc[mf][nf][3] + bb1, 0.f) * w1;
            }
        }
    }

    #pragma unroll
    for (int mf = 0; mf < 4; ++mf) {
        #pragma unroll
        for (int h = 0; h < 2; ++h) {
            float v = s[mf][h];
            v += __shfl_down_sync(0xffffffffu, v, 1);
            v += __shfl_down_sync(0xffffffffu, v, 2);
            s[mf][h] = v;
        }
    }
    __syncthreads();
    if (t == 0) {
        #pragma unroll
        for (int mf = 0; mf < 4; ++mf) {
            const int r = warp_m * 64 + mf * 16 + g;
            red[r][warp_n] = s[mf][0];
            red[r + 8][warp_n] = s[mf][1];
        }
    }
    __syncthreads();
    if (tid < MT) {
        float v = red[tid][0] + red[tid][1] + red[tid][2] + red[tid][3];
        g_logits[m0 + tid] = v + b2[0];
    }
#endif // !HAS_TC05
}

// ---------------------------------------------------------------------------
// K2: per-batch boundary sample + scan + segment starts + fused scalars.
// ---------------------------------------------------------------------------
__global__ __launch_bounds__(1024) void scan_kernel(
    const float* __restrict__ noise_u, float* __restrict__ outs)
{
    const int b = blockIdx.x;
    const int tid = threadIdx.x;
    const int l0 = tid * 4;
    const int base = b * LL + l0;

    int hd[4];
    #pragma unroll
    for (int j = 0; j < 4; ++j) {
        float u = noise_u[base + j];
        float x = g_logits[base + j] + logf(u) - log1pf(-u);
        hd[j] = (x > 0.f) ? 1 : 0;
    }
    int p = hd[0] + hd[1] + hd[2] + hd[3];

    const int lane = tid & 31;
    const int warp = tid >> 5;
    int v = p;
    #pragma unroll
    for (int off = 1; off < 32; off <<= 1) {
        int n = __shfl_up_sync(0xffffffffu, v, off);
        if (lane >= off) v += n;
    }
    __shared__ int wsum[32];
    if (lane == 31) wsum[warp] = v;
    __syncthreads();
    if (warp == 0) {
        int w = wsum[lane];
        #pragma unroll
        for (int off = 1; off < 32; off <<= 1) {
            int n = __shfl_up_sync(0xffffffffu, w, off);
            if (lane >= off) w += n;
        }
        wsum[lane] = w;
    }
    __syncthreads();

    int excl = (warp ? wsum[warp - 1] : 0) + v - p;   // boundaries strictly before l0
    int run = excl;                                    // = seg id of current token
    if (tid == 0) g_segstart[b * LL] = 0;
    #pragma unroll
    for (int j = 0; j < 4; ++j) {
        if (hd[j]) {
            int nxt = l0 + j + 1;
            if (nxt < LL) g_segstart[b * LL + run + 1] = nxt;
        }
        run += hd[j];
    }
    if (tid == 1023) {
        g_bcnt[b] = run;
        g_nseg[b] = run - hd[3] + 1;
        __threadfence();
        int done = atomicAdd(&g_done, 1);
        if (done == BB - 1) {
            int nb = 0;
            #pragma unroll
            for (int i = 0; i < BB; ++i) nb += g_bcnt[i];
            float ratio = (float)nb / (float)NTOK;
            outs[0] = fmaxf(fabsf(ratio - 0.25f) - 0.05f, 0.f);
            outs[1] = (float)nb;
            outs[2] = (float)NTOK;
            atomicExch(&g_done, 0);
        }
    }
}

// ---------------------------------------------------------------------------
// K4: pooled output — one warp per OUTPUT row (b, s). Covers all rows.
// ---------------------------------------------------------------------------
__global__ __launch_bounds__(128) void pool_kernel(
    const float* __restrict__ hidden, float* __restrict__ out)
{
    const int gwarp = (blockIdx.x * blockDim.x + threadIdx.x) >> 5;
    const int lane = threadIdx.x & 31;
    const int b = gwarp >> 12;          // / LL
    const int s = gwarp & (LL - 1);     // % LL

    float4 acc[6];
    #pragma unroll
    for (int i = 0; i < 6; ++i) acc[i] = make_float4(0.f, 0.f, 0.f, 0.f);

    const int nseg = g_nseg[b];
    if (s < nseg) {
        const int start = g_segstart[b * LL + s];
        const int end = (s + 1 < nseg) ? g_segstart[b * LL + s + 1] : LL;
        const float4* row = (const float4*)(hidden + ((size_t)b * LL + start) * DD);
        #pragma unroll 2
        for (int j = start; j < end; ++j, row += DD / 4) {
            #pragma unroll
            for (int i = 0; i < 6; ++i) {
                float4 r = row[lane + 32 * i];
                acc[i].x += r.x; acc[i].y += r.y; acc[i].z += r.z; acc[i].w += r.w;
            }
        }
        const float inv = 1.0f / (float)(end - start);
        #pragma unroll
        for (int i = 0; i < 6; ++i) {
            acc[i].x *= inv; acc[i].y *= inv; acc[i].z *= inv; acc[i].w *= inv;
        }
    }

    float4* orow = (float4*)(out + ((size_t)b * LL + s) * DD);
    #pragma unroll
    for (int i = 0; i < 6; ++i) orow[lane + 32 * i] = acc[i];
}

// ---------------------------------------------------------------------------
extern "C" void kernel_launch(void* const* d_in, const int* in_sizes, int n_in,
                              void* d_out, int out_size) {
    const float* hidden  = (const float*)d_in[0];
    const float* W1      = (const float*)d_in[1];
    const float* b1      = (const float*)d_in[2];
    const float* W2      = (const float*)d_in[3];
    const float* b2      = (const float*)d_in[4];
    const float* noise_u = (const float*)d_in[5];
    float* out = (float*)d_out;

    // Which GEMM has a body in the loaded cubin? (host code runs at capture time)
    cudaFuncAttributes attr;
    cudaFuncGetAttributes(&attr, gemm_logits_tc05_kernel);
    const bool tc05_live = attr.numRegs > 24;

    if (tc05_live) {
        cudaFuncSetAttribute(gemm_logits_tc05_kernel,
                             cudaFuncAttributeMaxDynamicSharedMemorySize, SMEM_TOTAL);
        w1prep_kernel<<<(NUM_CHUNK * 2 * BBLK / 16) / 256, 256>>>(W1);
        gemm_logits_tc05_kernel<<<NTOK / 128, 256, SMEM_TOTAL>>>(hidden, b1, W2, b2);
    } else {
        gemm_logits_fb_kernel<<<NTOK / MT, 256>>>(hidden, W1, b1, W2, b2);
    }
    scan_kernel<<<BB, 1024>>>(noise_u, out + (out_size - 3));
    pool_kernel<<<NTOK / 4, 128>>>(hidden, out);
}